// round 11
// baseline (speedup 1.0000x reference)
#include <cuda_runtime.h>

#define NMAX 100000
#define D 32
#define MAXB 2048

// ---- persistent scratch (device globals; zero-initialized at load) ----
__device__ float    d_q[NMAX];        // q[n] = dinv[n] * (u . p[n] + c2)
__device__ float    d_sacc[NMAX];     // scalar accumulator, init = q (self loop)
__device__ float    d_dinv[NMAX];
__device__ int      d_deg[NMAX];      // starts 0; encode phase re-zeroes
__device__ double   d_part[MAXB][5];  // per-block x-moment partials
__device__ float    d_C;              // wb . gcn_b + bb
__device__ unsigned d_count;          // barrier arrive counter (returns to 0)
__device__ unsigned d_epoch;          // monotonic barrier epoch (replay-safe)

// epoch-based grid barrier (replay-safe: epoch is monotonic, base read before
// any arrive of this kernel; co-residency guaranteed by launch_bounds+grid).
__device__ __forceinline__ void gbar(unsigned base, unsigned tgt, unsigned nb) {
    __syncthreads();
    if (threadIdx.x == 0) {
        __threadfence();
        if (atomicAdd(&d_count, 1) == nb - 1) {
            atomicExch(&d_count, 0);
            __threadfence();
            atomicAdd(&d_epoch, 1);
        } else {
            while (atomicAdd(&d_epoch, 0) - base < tgt) __nanosleep(32);
        }
    }
    __syncthreads();
}

// ===========================================================================
// Kernel 1: P1 deg histogram + x moments | barrier | P2 fold + encode q
// ===========================================================================
__global__ void __launch_bounds__(256, 6) degenc_k(
    const float* __restrict__ x, const int* __restrict__ ei,
    const float* __restrict__ w1, const float* __restrict__ b1,
    const float* __restrict__ gam, const float* __restrict__ bet,
    const float* __restrict__ pa,
    const float* __restrict__ w2, const float* __restrict__ b2,
    const float* __restrict__ gw, const float* __restrict__ gb,
    const float* __restrict__ wb, const float* __restrict__ bb,
    int n, int E) {
    __shared__ float sA[2 * D], sB[D], sU[D], sV[D];
    __shared__ float sc2;
    __shared__ double sst[5];
    __shared__ double sred[8][5];
    __shared__ unsigned sbase;

    const int t = threadIdx.x;
    const unsigned nb = gridDim.x;
    const int g = blockIdx.x * 256 + t;
    const int T = nb * 256;
    const int nT8 = E >> 3;
    const int Etail = E & 7;

    if (t == 0) sbase = atomicAdd(&d_epoch, 0);
    __syncthreads();
    const unsigned base = sbase;

    // -------- P1: in-degree histogram (8 edges/thread) + x moments --------
    {
        const int4* d4 = (const int4*)(ei + E);
        for (int i = g; i < nT8; i += T) {
            int4 a = d4[2 * i];
            int4 b = d4[2 * i + 1];
            atomicAdd(&d_deg[a.x], 1); atomicAdd(&d_deg[a.y], 1);
            atomicAdd(&d_deg[a.z], 1); atomicAdd(&d_deg[a.w], 1);
            atomicAdd(&d_deg[b.x], 1); atomicAdd(&d_deg[b.y], 1);
            atomicAdd(&d_deg[b.z], 1); atomicAdd(&d_deg[b.w], 1);
        }
        if (g == 0)
            for (int k = 0; k < Etail; k++) atomicAdd(&d_deg[ei[E + nT8 * 8 + k]], 1);

        float s[5] = { 0.f, 0.f, 0.f, 0.f, 0.f };
        for (int i = g; i < n; i += T) {
            float2 xv = ((const float2*)x)[i];
            s[0] += xv.x; s[1] += xv.y;
            s[2] += xv.x * xv.x; s[3] += xv.y * xv.y; s[4] += xv.x * xv.y;
        }
#pragma unroll
        for (int o = 16; o; o >>= 1)
#pragma unroll
            for (int j = 0; j < 5; j++) s[j] += __shfl_xor_sync(0xffffffffu, s[j], o);
        if ((t & 31) == 0)
#pragma unroll
            for (int j = 0; j < 5; j++) sred[t >> 5][j] = (double)s[j];
        __syncthreads();
        if (t < 5) {
            double acc = 0.0;
#pragma unroll
            for (int w = 0; w < 8; w++) acc += sred[w][t];
            d_part[blockIdx.x][t] = acc;
        }
    }
    gbar(base, 1, nb);

    // -------- P2: fold constants + encode q --------
    {
        if (t < 160) {
            int c = t >> 5, k = t & 31;
            double a = 0.0;
            for (unsigned b = k; b < nb; b += 32) a += d_part[b][c];
#pragma unroll
            for (int o = 16; o; o >>= 1) a += __shfl_xor_sync(0xffffffffu, a, o);
            if (k == 0) sst[c] = a;
        }
        __syncthreads();
        if (t < D) {
            double invN = 1.0 / (double)n;
            double m0 = sst[0] * invN, m1 = sst[1] * invN;
            double v00 = sst[2] * invN - m0 * m0;
            double v11 = sst[3] * invN - m1 * m1;
            double v01 = sst[4] * invN - m0 * m1;
            float a0 = w1[2 * t], a1 = w1[2 * t + 1];
            float mean = (float)((double)a0 * m0 + (double)a1 * m1) + b1[t];
            float var  = (float)((double)a0 * a0 * v00 + 2.0 * (double)a0 * a1 * v01 +
                                 (double)a1 * a1 * v11);
            float scale = gam[t] * rsqrtf(var + 1e-5f);
            sA[2 * t]     = a0 * scale;
            sA[2 * t + 1] = a1 * scale;
            sB[t] = b1[t] * scale + bet[t] - mean * scale;
            float v = 0.f;
#pragma unroll
            for (int r = 0; r < D; r++) v = fmaf(wb[r], gw[r * D + t], v);
            sV[t] = v;
        }
        __syncthreads();
        if (t < D) {
            float u = 0.f;
#pragma unroll
            for (int r = 0; r < D; r++) u = fmaf(sV[r], w2[r * D + t], u);
            sU[t] = u;
            float cc = sV[t] * b2[t];
            float Cc = wb[t] * gb[t];
#pragma unroll
            for (int o = 16; o; o >>= 1) {
                cc += __shfl_xor_sync(0xffffffffu, cc, o);
                Cc += __shfl_xor_sync(0xffffffffu, Cc, o);
            }
            if (t == 0) {
                sc2 = cc;
                if (blockIdx.x == 0) d_C = Cc + bb[0];
            }
        }
        __syncthreads();

        float alpha = pa[0];
        for (int node = g; node < n; node += T) {
            float2 xv = ((const float2*)x)[node];
            int dg = __ldcg(&d_deg[node]);   // RED-produced: L2 only
            d_deg[node] = 0;                 // re-zero for next graph replay
            float dv = rsqrtf((float)dg + 1.0f);
            float acc = sc2;
#pragma unroll
            for (int k = 0; k < D; k++) {
                float h = fmaf(sA[2 * k], xv.x, fmaf(sA[2 * k + 1], xv.y, sB[k]));
                float p = h >= 0.f ? h : alpha * h;
                acc = fmaf(sU[k], p, acc);
            }
            float qv = dv * acc;
            d_q[node] = qv;
            d_sacc[node] = qv;               // self-loop prefolded
            d_dinv[node] = dv;
        }
    }
}

// ===========================================================================
// Kernel 2: P3 edge scatter | barrier | P4 score
// ===========================================================================
__global__ void __launch_bounds__(256, 6) scatsc_k(
    const int* __restrict__ ei, float* __restrict__ out, int n, int E) {
    __shared__ unsigned sbase;
    const int t = threadIdx.x;
    const unsigned nb = gridDim.x;
    const int g = blockIdx.x * 256 + t;
    const int T = nb * 256;
    const int nT8 = E >> 3;
    const int Etail = E & 7;

    if (t == 0) sbase = atomicAdd(&d_epoch, 0);
    __syncthreads();
    const unsigned base = sbase;

    // -------- P3: scatter (8 edges/thread) --------
    {
        const int4* s4 = (const int4*)ei;
        const int4* d4 = (const int4*)(ei + E);   // L2-hot from kernel 1
        for (int i = g; i < nT8; i += T) {
            int4 s0 = s4[2 * i];
            int4 s1 = s4[2 * i + 1];
            int4 t0 = d4[2 * i];
            int4 t1 = d4[2 * i + 1];
            float q0 = __ldg(&d_q[s0.x]);
            float q1 = __ldg(&d_q[s0.y]);
            float q2 = __ldg(&d_q[s0.z]);
            float q3 = __ldg(&d_q[s0.w]);
            float q4 = __ldg(&d_q[s1.x]);
            float q5 = __ldg(&d_q[s1.y]);
            float q6 = __ldg(&d_q[s1.z]);
            float q7 = __ldg(&d_q[s1.w]);
            atomicAdd(&d_sacc[t0.x], q0);
            atomicAdd(&d_sacc[t0.y], q1);
            atomicAdd(&d_sacc[t0.z], q2);
            atomicAdd(&d_sacc[t0.w], q3);
            atomicAdd(&d_sacc[t1.x], q4);
            atomicAdd(&d_sacc[t1.y], q5);
            atomicAdd(&d_sacc[t1.z], q6);
            atomicAdd(&d_sacc[t1.w], q7);
        }
        if (g == 0)
            for (int k = 0; k < Etail; k++) {
                int e = nT8 * 8 + k;
                atomicAdd(&d_sacc[ei[E + e]], __ldg(&d_q[ei[e]]));
            }
    }
    gbar(base, 1, nb);

    // -------- P4: score --------
    {
        float C = d_C;
        int n4 = n >> 2;
        for (int i = g; i < n4; i += T) {
            float4 dv = ((const float4*)d_dinv)[i];
            float s0 = __ldcg(&d_sacc[4 * i]);       // RED-produced: L2 only
            float s1 = __ldcg(&d_sacc[4 * i + 1]);
            float s2 = __ldcg(&d_sacc[4 * i + 2]);
            float s3 = __ldcg(&d_sacc[4 * i + 3]);
            float4 o;
            o.x = fmaf(dv.x, s0, C);
            o.y = fmaf(dv.y, s1, C);
            o.z = fmaf(dv.z, s2, C);
            o.w = fmaf(dv.w, s3, C);
            ((float4*)out)[i] = o;
        }
        if (g == 0)
            for (int k = n4 * 4; k < n; k++)
                out[k] = fmaf(d_dinv[k], __ldcg(&d_sacc[k]), C);
    }
}

// ---------------------------------------------------------------------------
extern "C" void kernel_launch(void* const* d_in, const int* in_sizes, int n_in,
                              void* d_out, int out_size) {
    const float* x   = (const float*)d_in[0];
    const int*   ei  = (const int*)d_in[1];      // int32 (JAX x64 disabled)
    const float* w1  = (const float*)d_in[2];
    const float* b1  = (const float*)d_in[3];
    const float* gam = (const float*)d_in[4];
    const float* bet = (const float*)d_in[5];
    const float* pa  = (const float*)d_in[6];
    const float* w2  = (const float*)d_in[7];
    const float* b2  = (const float*)d_in[8];
    const float* gw  = (const float*)d_in[9];
    const float* gb  = (const float*)d_in[10];
    const float* wb  = (const float*)d_in[11];
    const float* bb  = (const float*)d_in[12];
    int n = in_sizes[0] / 2;
    int E = in_sizes[1] / 2;

    int dev = 0, sms = 148;
    cudaGetDevice(&dev);
    cudaDeviceGetAttribute(&sms, cudaDevAttrMultiProcessorCount, dev);
    int nb = sms * 6;                  // co-resident per __launch_bounds__(256,6)
    if (nb > MAXB) nb = MAXB;

    degenc_k<<<nb, 256>>>(x, ei, w1, b1, gam, bet, pa, w2, b2, gw, gb, wb, bb, n, E);
    scatsc_k<<<nb, 256>>>(ei, (float*)d_out, n, E);
}

// round 13
// speedup vs baseline: 1.5486x; 1.5486x over previous
#include <cuda_runtime.h>

#define NMAX 100000
#define D 32
#define NBN ((NMAX + 255) / 256)   // 391 node-blocks

// ---- persistent scratch (device globals; zero-initialized at load) ----
__device__ float  d_q[NMAX];        // q[n] = dinv[n] * (u . p[n] + c2)
__device__ float  d_sacc[NMAX];     // scalar accumulator, init = q (self loop)
__device__ float  d_dinv[NMAX];
__device__ int    d_deg[NMAX];      // starts 0; encode_k re-zeroes after read
__device__ double d_part[NBN][5];   // per-block x-moment partials
__device__ float  d_C;              // wb . gcn_b + bb

// ---------------------------------------------------------------------------
// degstats_k: in-degree histogram (8 edges/thread) + x-moment partials.
// No grid-dep sync needed: touches only buffers not written by the previous
// kernel in stream order (prior replay's score writes out[] only).
__global__ void __launch_bounds__(256) degstats_k(
    const int* __restrict__ dst, int nT8, int Etail,
    const float* __restrict__ x, int n, int nbn) {
    int t = threadIdx.x;
    int i = blockIdx.x * 256 + t;
    if (i < nT8) {
        const int4* d4 = (const int4*)dst;
        int4 a = d4[2 * i];
        int4 b = d4[2 * i + 1];
        atomicAdd(&d_deg[a.x], 1); atomicAdd(&d_deg[a.y], 1);
        atomicAdd(&d_deg[a.z], 1); atomicAdd(&d_deg[a.w], 1);
        atomicAdd(&d_deg[b.x], 1); atomicAdd(&d_deg[b.y], 1);
        atomicAdd(&d_deg[b.z], 1); atomicAdd(&d_deg[b.w], 1);
    }
    if (i == 0)
        for (int k = 0; k < Etail; k++) atomicAdd(&d_deg[dst[nT8 * 8 + k]], 1);

    // stats: first nbn blocks, one node per thread
    if (blockIdx.x < nbn) {
        __shared__ double sred[8][5];
        int node = blockIdx.x * 256 + t;
        float a = 0.f, b = 0.f;
        if (node < n) {
            float2 xv = ((const float2*)x)[node];
            a = xv.x; b = xv.y;
        }
        float s[5] = { a, b, a * a, b * b, a * b };
#pragma unroll
        for (int o = 16; o; o >>= 1)
#pragma unroll
            for (int j = 0; j < 5; j++) s[j] += __shfl_xor_sync(0xffffffffu, s[j], o);
        if ((t & 31) == 0)
#pragma unroll
            for (int j = 0; j < 5; j++) sred[t >> 5][j] = (double)s[j];
        __syncthreads();
        if (t < 5) {
            double acc = 0.0;
#pragma unroll
            for (int w = 0; w < 8; w++) acc += sred[w][t];
            d_part[blockIdx.x][t] = acc;
        }
    }
}

// encode_k: prologue loads weights (independent), THEN grid-dep sync, then
// fold BN/v/u/c2/C from d_part/d_deg (dependent on degstats_k).
__global__ void __launch_bounds__(256) encode_k(
    const float* __restrict__ x,
    const float* __restrict__ w1, const float* __restrict__ b1,
    const float* __restrict__ gam, const float* __restrict__ bet,
    const float* __restrict__ pa,
    const float* __restrict__ w2, const float* __restrict__ b2,
    const float* __restrict__ gw, const float* __restrict__ gb,
    const float* __restrict__ wb, const float* __restrict__ bb,
    int n, int nbn) {
    __shared__ float sA[2 * D], sB[D], sU[D], sV[D];
    __shared__ float sc2;
    __shared__ double sst[5];
    int t = threadIdx.x;

    // ---- independent prologue: stage weights + x (inputs only) ----
    float w1a = 0.f, w1b = 0.f, vb1 = 0.f, vgam = 0.f, vbet = 0.f;
    if (t < D) {
        w1a = w1[2 * t]; w1b = w1[2 * t + 1];
        vb1 = b1[t]; vgam = gam[t]; vbet = bet[t];
        float v = 0.f;
#pragma unroll
        for (int r = 0; r < D; r++) v = fmaf(wb[r], gw[r * D + t], v);
        sV[t] = v;
    }
    float alpha = pa[0];
    int node = blockIdx.x * 256 + t;
    float2 xv = make_float2(0.f, 0.f);
    if (node < n) xv = ((const float2*)x)[node];
    __syncthreads();
    if (t < D) {
        float u = 0.f;
#pragma unroll
        for (int r = 0; r < D; r++) u = fmaf(sV[r], w2[r * D + t], u);
        sU[t] = u;
        float cc = sV[t] * b2[t];
        float Cc = wb[t] * gb[t];
#pragma unroll
        for (int o = 16; o; o >>= 1) {
            cc += __shfl_xor_sync(0xffffffffu, cc, o);
            Cc += __shfl_xor_sync(0xffffffffu, Cc, o);
        }
        if (t == 0) {
            sc2 = cc;
            if (blockIdx.x == 0) d_C = Cc + bb[0];
        }
    }

    // ---- wait for degstats_k results ----
    cudaGridDependencySynchronize();

    if (t < 160) {
        int c = t >> 5, k = t & 31;
        double a = 0.0;
        for (int b = k; b < nbn; b += 32) a += d_part[b][c];
#pragma unroll
        for (int o = 16; o; o >>= 1) a += __shfl_xor_sync(0xffffffffu, a, o);
        if (k == 0) sst[c] = a;
    }
    __syncthreads();

    if (t < D) {
        double invN = 1.0 / (double)n;
        double m0 = sst[0] * invN, m1 = sst[1] * invN;
        double v00 = sst[2] * invN - m0 * m0;
        double v11 = sst[3] * invN - m1 * m1;
        double v01 = sst[4] * invN - m0 * m1;
        float mean = (float)((double)w1a * m0 + (double)w1b * m1) + vb1;
        float var  = (float)((double)w1a * w1a * v00 + 2.0 * (double)w1a * w1b * v01 +
                             (double)w1b * w1b * v11);
        float scale = vgam * rsqrtf(var + 1e-5f);
        sA[2 * t]     = w1a * scale;
        sA[2 * t + 1] = w1b * scale;
        sB[t] = vb1 * scale + vbet - mean * scale;
    }
    __syncthreads();

    if (node < n) {
        int dg = __ldcg(&d_deg[node]);        // RED-produced (L2)
        d_deg[node] = 0;                      // re-zero for next graph replay
        float dv = rsqrtf((float)dg + 1.0f);
        float acc = sc2;
#pragma unroll
        for (int k = 0; k < D; k++) {
            float h = fmaf(sA[2 * k], xv.x, fmaf(sA[2 * k + 1], xv.y, sB[k]));
            float p = h >= 0.f ? h : alpha * h;
            acc = fmaf(sU[k], p, acc);
        }
        float qv = dv * acc;
        d_q[node] = qv;
        d_sacc[node] = qv;                    // self-loop prefolded
        d_dinv[node] = dv;
    }
}

// scatter_k: prologue loads edge indices (inputs), THEN sync, then gather+RED.
__global__ void __launch_bounds__(256) scatter_k(const int* __restrict__ ei, int E,
                                                 int nT8, int Etail) {
    int i = blockIdx.x * 256 + threadIdx.x;
    int4 s0, s1, t0, t1;
    bool act = i < nT8;
    if (act) {
        const int4* s4 = (const int4*)ei;
        const int4* d4 = (const int4*)(ei + E);
        s0 = s4[2 * i];
        s1 = s4[2 * i + 1];
        t0 = d4[2 * i];
        t1 = d4[2 * i + 1];
    }

    cudaGridDependencySynchronize();          // wait for encode_k's q/sacc

    if (act) {
        float q0 = __ldg(&d_q[s0.x]);
        float q1 = __ldg(&d_q[s0.y]);
        float q2 = __ldg(&d_q[s0.z]);
        float q3 = __ldg(&d_q[s0.w]);
        float q4 = __ldg(&d_q[s1.x]);
        float q5 = __ldg(&d_q[s1.y]);
        float q6 = __ldg(&d_q[s1.z]);
        float q7 = __ldg(&d_q[s1.w]);
        atomicAdd(&d_sacc[t0.x], q0);
        atomicAdd(&d_sacc[t0.y], q1);
        atomicAdd(&d_sacc[t0.z], q2);
        atomicAdd(&d_sacc[t0.w], q3);
        atomicAdd(&d_sacc[t1.x], q4);
        atomicAdd(&d_sacc[t1.y], q5);
        atomicAdd(&d_sacc[t1.z], q6);
        atomicAdd(&d_sacc[t1.w], q7);
    }
    if (i == 0)
        for (int k = 0; k < Etail; k++) {
            int e = nT8 * 8 + k;
            atomicAdd(&d_sacc[ei[E + e]], __ldg(&d_q[ei[e]]));
        }
}

// score_k: prologue loads dinv (written by encode_k, already complete),
// THEN sync on scatter_k, then read sacc and store.
__global__ void __launch_bounds__(128) score_k(float* __restrict__ out, int n4, int n) {
    int i = blockIdx.x * 128 + threadIdx.x;
    float4 dv = make_float4(0.f, 0.f, 0.f, 0.f);
    bool act = i < n4;
    if (act) dv = ((const float4*)d_dinv)[i];

    cudaGridDependencySynchronize();          // wait for scatter_k's REDs

    float C = d_C;
    if (act) {
        float s0 = __ldcg(&d_sacc[4 * i]);    // RED-produced (L2)
        float s1 = __ldcg(&d_sacc[4 * i + 1]);
        float s2 = __ldcg(&d_sacc[4 * i + 2]);
        float s3 = __ldcg(&d_sacc[4 * i + 3]);
        float4 o;
        o.x = fmaf(dv.x, s0, C);
        o.y = fmaf(dv.y, s1, C);
        o.z = fmaf(dv.z, s2, C);
        o.w = fmaf(dv.w, s3, C);
        ((float4*)out)[i] = o;
    }
    if (i == 0)
        for (int k = n4 * 4; k < n; k++)
            out[k] = fmaf(d_dinv[k], __ldcg(&d_sacc[k]), C);
}

// ---------------------------------------------------------------------------
static void launch_pdl(void* fn, dim3 grid, dim3 block, void** args) {
    cudaLaunchConfig_t cfg = {};
    cfg.gridDim = grid;
    cfg.blockDim = block;
    cfg.dynamicSmemBytes = 0;
    cfg.stream = 0;
    cudaLaunchAttribute attr[1];
    attr[0].id = cudaLaunchAttributeProgrammaticStreamSerialization;
    attr[0].val.programmaticStreamSerializationAllowed = 1;
    cfg.attrs = attr;
    cfg.numAttrs = 1;
    cudaLaunchKernelExC(&cfg, fn, args);
}

extern "C" void kernel_launch(void* const* d_in, const int* in_sizes, int n_in,
                              void* d_out, int out_size) {
    const float* x   = (const float*)d_in[0];
    const int*   ei  = (const int*)d_in[1];      // int32 (JAX x64 disabled)
    const float* w1  = (const float*)d_in[2];
    const float* b1  = (const float*)d_in[3];
    const float* gam = (const float*)d_in[4];
    const float* bet = (const float*)d_in[5];
    const float* pa  = (const float*)d_in[6];
    const float* w2  = (const float*)d_in[7];
    const float* b2  = (const float*)d_in[8];
    const float* gw  = (const float*)d_in[9];
    const float* gb  = (const float*)d_in[10];
    const float* wb  = (const float*)d_in[11];
    const float* bb  = (const float*)d_in[12];
    int n = in_sizes[0] / 2;
    int E = in_sizes[1] / 2;
    int nT8 = E >> 3;                 // 8 edges per thread
    int Etail = E & 7;
    int nbn = (n + 255) / 256;
    int ebn = (nT8 + 255) / 256;
    if (ebn < nbn) ebn = nbn;         // edge grid must cover the stats blocks
    int n4 = n >> 2;
    int sbn = (n4 + 127) / 128;
    float* out = (float*)d_out;

    const int* dst = ei + E;
    {   // degstats (no PDL needed on first kernel, but harmless for replay overlap)
        void* a[] = { (void*)&dst, &nT8, &Etail, (void*)&x, &n, &nbn };
        launch_pdl((void*)degstats_k, dim3(ebn), dim3(256), a);
    }
    {
        void* a[] = { (void*)&x, (void*)&w1, (void*)&b1, (void*)&gam, (void*)&bet,
                      (void*)&pa, (void*)&w2, (void*)&b2, (void*)&gw, (void*)&gb,
                      (void*)&wb, (void*)&bb, &n, &nbn };
        launch_pdl((void*)encode_k, dim3(nbn), dim3(256), a);
    }
    {
        void* a[] = { (void*)&ei, &E, &nT8, &Etail };
        launch_pdl((void*)scatter_k, dim3((nT8 + 255) / 256), dim3(256), a);
    }
    {
        void* a[] = { (void*)&out, &n4, &n };
        launch_pdl((void*)score_k, dim3(sbn), dim3(128), a);
    }
}

// round 14
// speedup vs baseline: 1.6074x; 1.0379x over previous
#include <cuda_runtime.h>

#define NMAX 100000
#define D 32
#define NBN ((NMAX + 255) / 256)   // 391 node-blocks

// ---- persistent scratch (device globals; zero-initialized at load) ----
__device__ float  d_q[NMAX];        // q[n] = dinv[n] * (u . p[n] + c2)
__device__ float  d_sacc[NMAX];     // scalar accumulator, init = q (self loop)
__device__ float  d_dinv[NMAX];
__device__ int    d_deg[NMAX];      // starts 0; encode_k re-zeroes after read
__device__ double d_part[NBN][5];   // per-block x-moment partials
__device__ float  d_C;              // wb . gcn_b + bb

// ---------------------------------------------------------------------------
// degstats_k: trigger@start (encode may launch + run its input-only prologue).
// Touches only d_deg/d_part, which the concurrent encode prologue never reads.
__global__ void __launch_bounds__(256) degstats_k(
    const int* __restrict__ dst, int nT8, int Etail,
    const float* __restrict__ x, int n, int nbn) {
    cudaTriggerProgrammaticLaunchCompletion();
    int t = threadIdx.x;
    int i = blockIdx.x * 256 + t;
    if (i < nT8) {
        const int4* d4 = (const int4*)dst;
        int4 a = d4[2 * i];
        int4 b = d4[2 * i + 1];
        atomicAdd(&d_deg[a.x], 1); atomicAdd(&d_deg[a.y], 1);
        atomicAdd(&d_deg[a.z], 1); atomicAdd(&d_deg[a.w], 1);
        atomicAdd(&d_deg[b.x], 1); atomicAdd(&d_deg[b.y], 1);
        atomicAdd(&d_deg[b.z], 1); atomicAdd(&d_deg[b.w], 1);
    }
    if (i == 0)
        for (int k = 0; k < Etail; k++) atomicAdd(&d_deg[dst[nT8 * 8 + k]], 1);

    // stats: first nbn blocks, one node per thread
    if (blockIdx.x < nbn) {
        __shared__ double sred[8][5];
        int node = blockIdx.x * 256 + t;
        float a = 0.f, b = 0.f;
        if (node < n) {
            float2 xv = ((const float2*)x)[node];
            a = xv.x; b = xv.y;
        }
        float s[5] = { a, b, a * a, b * b, a * b };
#pragma unroll
        for (int o = 16; o; o >>= 1)
#pragma unroll
            for (int j = 0; j < 5; j++) s[j] += __shfl_xor_sync(0xffffffffu, s[j], o);
        if ((t & 31) == 0)
#pragma unroll
            for (int j = 0; j < 5; j++) sred[t >> 5][j] = (double)s[j];
        __syncthreads();
        if (t < 5) {
            double acc = 0.0;
#pragma unroll
            for (int w = 0; w < 8; w++) acc += sred[w][t];
            d_part[blockIdx.x][t] = acc;
        }
    }
}

// encode_k: trigger@start; prologue (inputs only) overlaps degstats; all reads
// of d_part/d_deg and writes of d_q/d_sacc/d_dinv are after the grid-dep sync.
__global__ void __launch_bounds__(256) encode_k(
    const float* __restrict__ x,
    const float* __restrict__ w1, const float* __restrict__ b1,
    const float* __restrict__ gam, const float* __restrict__ bet,
    const float* __restrict__ pa,
    const float* __restrict__ w2, const float* __restrict__ b2,
    const float* __restrict__ gw, const float* __restrict__ gb,
    const float* __restrict__ wb, const float* __restrict__ bb,
    int n, int nbn) {
    cudaTriggerProgrammaticLaunchCompletion();
    __shared__ float sA[2 * D], sB[D], sU[D], sV[D];
    __shared__ float sc2;
    __shared__ double sst[5];
    int t = threadIdx.x;

    // ---- independent prologue: stage weights + x (inputs only) ----
    float w1a = 0.f, w1b = 0.f, vb1 = 0.f, vgam = 0.f, vbet = 0.f;
    if (t < D) {
        w1a = w1[2 * t]; w1b = w1[2 * t + 1];
        vb1 = b1[t]; vgam = gam[t]; vbet = bet[t];
        float v = 0.f;
#pragma unroll
        for (int r = 0; r < D; r++) v = fmaf(wb[r], gw[r * D + t], v);
        sV[t] = v;
    }
    float alpha = pa[0];
    int node = blockIdx.x * 256 + t;
    float2 xv = make_float2(0.f, 0.f);
    if (node < n) xv = ((const float2*)x)[node];
    __syncthreads();
    if (t < D) {
        float u = 0.f;
#pragma unroll
        for (int r = 0; r < D; r++) u = fmaf(sV[r], w2[r * D + t], u);
        sU[t] = u;
        float cc = sV[t] * b2[t];
        float Cc = wb[t] * gb[t];
#pragma unroll
        for (int o = 16; o; o >>= 1) {
            cc += __shfl_xor_sync(0xffffffffu, cc, o);
            Cc += __shfl_xor_sync(0xffffffffu, Cc, o);
        }
        if (t == 0) {
            sc2 = cc;
            if (blockIdx.x == 0) d_C = Cc + bb[0];  // same value every replay
        }
    }

    // ---- wait for degstats_k results ----
    cudaGridDependencySynchronize();

    if (t < 160) {
        int c = t >> 5, k = t & 31;
        double a = 0.0;
        for (int b = k; b < nbn; b += 32) a += d_part[b][c];
#pragma unroll
        for (int o = 16; o; o >>= 1) a += __shfl_xor_sync(0xffffffffu, a, o);
        if (k == 0) sst[c] = a;
    }
    __syncthreads();

    if (t < D) {
        double invN = 1.0 / (double)n;
        double m0 = sst[0] * invN, m1 = sst[1] * invN;
        double v00 = sst[2] * invN - m0 * m0;
        double v11 = sst[3] * invN - m1 * m1;
        double v01 = sst[4] * invN - m0 * m1;
        float mean = (float)((double)w1a * m0 + (double)w1b * m1) + vb1;
        float var  = (float)((double)w1a * w1a * v00 + 2.0 * (double)w1a * w1b * v01 +
                             (double)w1b * w1b * v11);
        float scale = vgam * rsqrtf(var + 1e-5f);
        sA[2 * t]     = w1a * scale;
        sA[2 * t + 1] = w1b * scale;
        sB[t] = vb1 * scale + vbet - mean * scale;
    }
    __syncthreads();

    if (node < n) {
        int dg = __ldcg(&d_deg[node]);        // RED-produced (L2)
        d_deg[node] = 0;                      // re-zero for next graph replay
        float dv = rsqrtf((float)dg + 1.0f);
        float acc = sc2;
#pragma unroll
        for (int k = 0; k < D; k++) {
            float h = fmaf(sA[2 * k], xv.x, fmaf(sA[2 * k + 1], xv.y, sB[k]));
            float p = h >= 0.f ? h : alpha * h;
            acc = fmaf(sU[k], p, acc);
        }
        float qv = dv * acc;
        d_q[node] = qv;
        d_sacc[node] = qv;                    // self-loop prefolded
        d_dinv[node] = dv;
    }
}

// scatter_k: trigger@start; prologue loads edge indices (inputs only); gathers
// and REDs after the sync on encode_k.
__global__ void __launch_bounds__(256) scatter_k(const int* __restrict__ ei, int E,
                                                 int nT8, int Etail) {
    cudaTriggerProgrammaticLaunchCompletion();
    int i = blockIdx.x * 256 + threadIdx.x;
    int4 s0, s1, t0, t1;
    bool act = i < nT8;
    if (act) {
        const int4* s4 = (const int4*)ei;
        const int4* d4 = (const int4*)(ei + E);
        s0 = s4[2 * i];
        s1 = s4[2 * i + 1];
        t0 = d4[2 * i];
        t1 = d4[2 * i + 1];
    }

    cudaGridDependencySynchronize();          // wait for encode_k's q/sacc

    if (act) {
        float q0 = __ldg(&d_q[s0.x]);
        float q1 = __ldg(&d_q[s0.y]);
        float q2 = __ldg(&d_q[s0.z]);
        float q3 = __ldg(&d_q[s0.w]);
        float q4 = __ldg(&d_q[s1.x]);
        float q5 = __ldg(&d_q[s1.y]);
        float q6 = __ldg(&d_q[s1.z]);
        float q7 = __ldg(&d_q[s1.w]);
        atomicAdd(&d_sacc[t0.x], q0);
        atomicAdd(&d_sacc[t0.y], q1);
        atomicAdd(&d_sacc[t0.z], q2);
        atomicAdd(&d_sacc[t0.w], q3);
        atomicAdd(&d_sacc[t1.x], q4);
        atomicAdd(&d_sacc[t1.y], q5);
        atomicAdd(&d_sacc[t1.z], q6);
        atomicAdd(&d_sacc[t1.w], q7);
    }
    if (i == 0)
        for (int k = 0; k < Etail; k++) {
            int e = nT8 * 8 + k;
            atomicAdd(&d_sacc[ei[E + e]], __ldg(&d_q[ei[e]]));
        }
}

// score_k: NO early trigger (implicit trigger at completion serializes the
// replay boundary — next degstats/encode touch d_sacc's producers). All reads
// after the sync on scatter_k (transitively guarantees encode_k done).
__global__ void __launch_bounds__(128) score_k(float* __restrict__ out, int n4, int n) {
    int i = blockIdx.x * 128 + threadIdx.x;

    cudaGridDependencySynchronize();          // wait for scatter_k's REDs

    float C = d_C;
    if (i < n4) {
        float4 dv = ((const float4*)d_dinv)[i];
        float s0 = __ldcg(&d_sacc[4 * i]);    // RED-produced (L2)
        float s1 = __ldcg(&d_sacc[4 * i + 1]);
        float s2 = __ldcg(&d_sacc[4 * i + 2]);
        float s3 = __ldcg(&d_sacc[4 * i + 3]);
        float4 o;
        o.x = fmaf(dv.x, s0, C);
        o.y = fmaf(dv.y, s1, C);
        o.z = fmaf(dv.z, s2, C);
        o.w = fmaf(dv.w, s3, C);
        ((float4*)out)[i] = o;
    }
    if (i == 0)
        for (int k = n4 * 4; k < n; k++)
            out[k] = fmaf(d_dinv[k], __ldcg(&d_sacc[k]), C);
}

// ---------------------------------------------------------------------------
static void launch_pdl(void* fn, dim3 grid, dim3 block, void** args) {
    cudaLaunchConfig_t cfg = {};
    cfg.gridDim = grid;
    cfg.blockDim = block;
    cfg.dynamicSmemBytes = 0;
    cfg.stream = 0;
    cudaLaunchAttribute attr[1];
    attr[0].id = cudaLaunchAttributeProgrammaticStreamSerialization;
    attr[0].val.programmaticStreamSerializationAllowed = 1;
    cfg.attrs = attr;
    cfg.numAttrs = 1;
    cudaLaunchKernelExC(&cfg, fn, args);
}

extern "C" void kernel_launch(void* const* d_in, const int* in_sizes, int n_in,
                              void* d_out, int out_size) {
    const float* x   = (const float*)d_in[0];
    const int*   ei  = (const int*)d_in[1];      // int32 (JAX x64 disabled)
    const float* w1  = (const float*)d_in[2];
    const float* b1  = (const float*)d_in[3];
    const float* gam = (const float*)d_in[4];
    const float* bet = (const float*)d_in[5];
    const float* pa  = (const float*)d_in[6];
    const float* w2  = (const float*)d_in[7];
    const float* b2  = (const float*)d_in[8];
    const float* gw  = (const float*)d_in[9];
    const float* gb  = (const float*)d_in[10];
    const float* wb  = (const float*)d_in[11];
    const float* bb  = (const float*)d_in[12];
    int n = in_sizes[0] / 2;
    int E = in_sizes[1] / 2;
    int nT8 = E >> 3;                 // 8 edges per thread
    int Etail = E & 7;
    int nbn = (n + 255) / 256;
    int ebn = (nT8 + 255) / 256;
    if (ebn < nbn) ebn = nbn;         // edge grid must cover the stats blocks
    int n4 = n >> 2;
    int sbn = (n4 + 127) / 128;
    float* out = (float*)d_out;

    const int* dst = ei + E;
    {
        void* a[] = { (void*)&dst, &nT8, &Etail, (void*)&x, &n, &nbn };
        launch_pdl((void*)degstats_k, dim3(ebn), dim3(256), a);
    }
    {
        void* a[] = { (void*)&x, (void*)&w1, (void*)&b1, (void*)&gam, (void*)&bet,
                      (void*)&pa, (void*)&w2, (void*)&b2, (void*)&gw, (void*)&gb,
                      (void*)&wb, (void*)&bb, &n, &nbn };
        launch_pdl((void*)encode_k, dim3(nbn), dim3(256), a);
    }
    {
        void* a[] = { (void*)&ei, &E, &nT8, &Etail };
        launch_pdl((void*)scatter_k, dim3((nT8 + 255) / 256), dim3(256), a);
    }
    {
        void* a[] = { (void*)&out, &n4, &n };
        launch_pdl((void*)score_k, dim3(sbn), dim3(128), a);
    }
}